// round 11
// baseline (speedup 1.0000x reference)
#include <cuda_runtime.h>
#include <math.h>

#define BB 8
#define LL 20
#define ND 2048           // N
#define FF 64             // F
#define NSQ (ND*ND)       // 4194304 = 2^22
#define CAP (1<<19)       // candidate capacity per batch
#define KSPLIT 8
#define MROWS (BB*FF)     // 512

// ---------------- scratch (static device, no allocation) ----------------
__device__ double g_m2[BB*LL*FF];
__device__ int    g_k[BB];
__device__ float  g_Xn [BB*ND*FF];        // normalized x_last, [b][n][f]
__device__ float  g_XnT[BB*FF*ND];        // transposed,        [b*64+f][n]
__device__ float  g_Tmat[MROWS*ND];       // t = Xn^T @ prior
__device__ float  g_part[KSPLIT*MROWS*ND];// split-K partials (33.5 MB)
__device__ unsigned g_hist1[BB*4096];
__device__ unsigned g_hist2[BB*4096];
__device__ unsigned g_cand[BB*CAP];
__device__ unsigned g_cand_cnt[BB];
__device__ unsigned g_thresh[BB];

__device__ __forceinline__ unsigned f2o(float f) {
    unsigned u = __float_as_uint(f);
    return (u & 0x80000000u) ? ~u : (u | 0x80000000u);
}
__device__ __forceinline__ unsigned smem_u32(const void* p) {
    return (unsigned)__cvta_generic_to_shared(p);
}
__device__ __forceinline__ void cp16(unsigned dst, const void* src) {
    asm volatile("cp.async.cg.shared.global [%0], [%1], 16;\n" :: "r"(dst), "l"(src));
}
#define CP_COMMIT() asm volatile("cp.async.commit_group;\n" ::: "memory")
#define CP_WAIT0()  asm volatile("cp.async.wait_group 0;\n" ::: "memory")
#define CP_WAIT1()  asm volatile("cp.async.wait_group 1;\n" ::: "memory")

// ---------------- prep: mean (blocks 0..159) + norm (160..415) + zero (416..423)
__global__ __launch_bounds__(256) void prep_kernel(const float* __restrict__ x_seq) {
    int tid = threadIdx.x;
    if (blockIdx.x < BB*LL) {
        // ---- mean over N (double accumulation) ----
        __shared__ double p[4][64];
        int bl = blockIdx.x;
        int f = tid & 63, j = tid >> 6;
        const float* base = x_seq + (size_t)bl * ND * FF;
        double s = 0.0;
        int n0 = j * 512;
        for (int n = n0; n < n0 + 512; n++) s += (double)base[(size_t)n * FF + f];
        p[j][f] = s;
        __syncthreads();
        if (j == 0) {
            double t = (p[0][f] + p[1][f]) + (p[2][f] + p[3][f]);
            g_m2[bl * FF + f] = t * (1.0 / ND);
        }
    } else if (blockIdx.x < BB*LL + 256) {
        // ---- normalize 64 rows of one batch; smem transpose for XnT ----
        __shared__ float sm[64][65];
        int bid = blockIdx.x - BB*LL;
        int warp = tid >> 5, lane = tid & 31;
        int b = bid >> 5;
        int n0 = (bid & 31) * 64;
        const float* xb = x_seq + ((size_t)(b*LL + (LL-1)) * ND + n0) * FF;
        for (int r = warp; r < 64; r += 8) {
            const float* row = xb + (size_t)r * FF;
            float v0 = row[lane], v1 = row[lane + 32];
            double ss = (double)v0*(double)v0 + (double)v1*(double)v1;
            #pragma unroll
            for (int o = 16; o; o >>= 1) ss += __shfl_xor_sync(0xffffffffu, ss, o);
            double d = sqrt(ss);
            if (d < 1e-12) d = 1e-12;
            float y0 = (float)((double)v0 / d), y1 = (float)((double)v1 / d);
            sm[r][lane] = y0; sm[r][lane + 32] = y1;
            size_t rb = (size_t)(b*ND + n0 + r) * FF;
            g_Xn[rb + lane]      = y0;
            g_Xn[rb + lane + 32] = y1;
        }
        __syncthreads();
        int f = tid >> 2, q = (tid & 3) * 16;
        float4* dst = reinterpret_cast<float4*>(&g_XnT[(size_t)(b*FF + f) * ND + n0 + q]);
        #pragma unroll
        for (int c = 0; c < 4; c++) {
            float4 v;
            v.x = sm[q + c*4 + 0][f];
            v.y = sm[q + c*4 + 1][f];
            v.z = sm[q + c*4 + 2][f];
            v.w = sm[q + c*4 + 3][f];
            dst[c] = v;
        }
    } else {
        int z = blockIdx.x - (BB*LL + 256);
        for (int i = z*256 + tid; i < BB*4096; i += 2048) { g_hist1[i] = 0; g_hist2[i] = 0; }
        if (z == 0 && tid < BB) g_cand_cnt[tid] = 0;
    }
}

// ---------------- tiny conv net -> k[b] (bit-exact, frozen) -----------------
__global__ __launch_bounds__(256) void net_kernel(
    const float* __restrict__ w1, const float* __restrict__ b1,
    const float* __restrict__ w2, const float* __restrict__ b2,
    const float* __restrict__ w3, const float* __restrict__ b3,
    const float* __restrict__ w4, const float* __restrict__ b4,
    const float* __restrict__ wout, const float* __restrict__ bout)
{
    __shared__ double sm[22][66];
    __shared__ double wsum[32][8];
    int tid = threadIdx.x;
    int lane = tid & 31, warp = tid >> 5;
    int b = blockIdx.x;

    for (int i = tid; i < 22*66; i += 256) ((double*)sm)[i] = 0.0;
    __syncthreads();
    for (int i = tid; i < LL*FF; i += 256) {
        int h = i / FF, w = i % FF;
        sm[h+1][w+1] = g_m2[(b*LL + h)*FF + w];
    }
    __syncthreads();

    double s[32];
    #pragma unroll
    for (int q = 0; q < 32; q++) s[q] = 0.0;

    for (int i = tid; i < LL*FF; i += 256) {
        int h = i / FF + 1, w = i % FF + 1;
        double c   = sm[h][w];
        double lft = sm[h][w-1], rgt = sm[h][w+1];
        double up  = sm[h-1][w], dn  = sm[h+1][w];
        double ul  = sm[h-1][w-1], ur = sm[h-1][w+1];
        double dl  = sm[h+1][w-1], dr = sm[h+1][w+1];
        #pragma unroll
        for (int ch = 0; ch < 8; ch++) {
            double v1 = (double)w1[ch]*c + (double)b1[ch];
            double v2 = (double)w2[ch*3+0]*lft + (double)w2[ch*3+1]*c + (double)w2[ch*3+2]*rgt + (double)b2[ch];
            double v3 = (double)w3[ch*3+0]*up  + (double)w3[ch*3+1]*c + (double)w3[ch*3+2]*dn  + (double)b3[ch];
            double v4 = (double)w4[ch*9+0]*ul + (double)w4[ch*9+1]*up + (double)w4[ch*9+2]*ur
                      + (double)w4[ch*9+3]*lft+ (double)w4[ch*9+4]*c  + (double)w4[ch*9+5]*rgt
                      + (double)w4[ch*9+6]*dl + (double)w4[ch*9+7]*dn + (double)w4[ch*9+8]*dr + (double)b4[ch];
            float f1 = (float)v1, f2 = (float)v2, f3 = (float)v3, f4 = (float)v4;
            s[ch]      += (double)(0.5f*f1*(1.0f + erff(f1*0.70710678f)));
            s[8  + ch] += (double)(0.5f*f2*(1.0f + erff(f2*0.70710678f)));
            s[16 + ch] += (double)(0.5f*f3*(1.0f + erff(f3*0.70710678f)));
            s[24 + ch] += (double)(0.5f*f4*(1.0f + erff(f4*0.70710678f)));
        }
    }
    #pragma unroll
    for (int q = 0; q < 32; q++) {
        double v = s[q];
        #pragma unroll
        for (int o = 16; o; o >>= 1) v += __shfl_down_sync(0xffffffffu, v, o);
        if (lane == 0) wsum[q][warp] = v;
    }
    __syncthreads();
    if (tid == 0) {
        double logit = (double)bout[0];
        for (int q = 0; q < 32; q++) {
            double t = 0.0;
            for (int w = 0; w < 8; w++) t += wsum[q][w];
            logit += (t * (1.0/(LL*FF))) * (double)wout[q];
        }
        double sig  = 1.0 / (1.0 + exp(-logit));
        double keep = 0.2 * sig;
        if (keep < 0.02) keep = 0.02;
        if (keep > 1.0)  keep = 1.0;
        float kf = __fmul_rn((float)keep, 4194304.0f);
        int k = (int)ceilf(kf);
        if (k < 1) k = 1;
        if (k > NSQ) k = NSQ;
        g_k[b] = k;
    }
}

// ---------------- GEMM1 split-K(8): part[z] = XnT @ prior, 3-stage pipeline -
__global__ __launch_bounds__(256, 2) void gemm1_kernel(const float* __restrict__ Bm) {
    const int BK = 16;
    __shared__ float As[3][BK][72];
    __shared__ __align__(16) float Bs[3][BK][128];
    int tid = threadIdx.x;
    int tx = tid & 15, ty = tid >> 4;
    int b = blockIdx.y, z = blockIdx.z;
    int bm0 = b * 64, bn0 = blockIdx.x * 128;
    int kbase = z * (ND / KSPLIT);          // 256-k chunk

    float acc[4][8];
    #pragma unroll
    for (int i = 0; i < 4; i++)
        #pragma unroll
        for (int j = 0; j < 8; j++) acc[i][j] = 0.f;

    int a_kk = tid >> 4, a_f4 = (tid & 15) * 4;
    int b_kk0 = tid >> 5,         b_c0 = (tid & 31) * 4;
    int b_kk1 = 8 + (tid >> 5),   b_c1 = b_c0;

    const int T = (ND / KSPLIT) / BK;       // 16 tiles
    #pragma unroll
    for (int pt = 0; pt < 2; pt++) {
        int k0 = kbase + pt * BK;
        cp16(smem_u32(&As[pt][a_kk][a_f4]),  &g_Xn[((size_t)b*ND + k0 + a_kk)*FF + a_f4]);
        cp16(smem_u32(&Bs[pt][b_kk0][b_c0]), &Bm[(size_t)(k0 + b_kk0)*ND + bn0 + b_c0]);
        cp16(smem_u32(&Bs[pt][b_kk1][b_c1]), &Bm[(size_t)(k0 + b_kk1)*ND + bn0 + b_c1]);
        CP_COMMIT();
    }

    for (int t = 0; t < T; t++) {
        if (t == T - 1) { CP_WAIT0(); } else { CP_WAIT1(); }
        __syncthreads();
        int buf = t % 3;
        if (t + 2 < T) {
            int k0 = kbase + (t + 2) * BK, nb = (t + 2) % 3;
            cp16(smem_u32(&As[nb][a_kk][a_f4]),  &g_Xn[((size_t)b*ND + k0 + a_kk)*FF + a_f4]);
            cp16(smem_u32(&Bs[nb][b_kk0][b_c0]), &Bm[(size_t)(k0 + b_kk0)*ND + bn0 + b_c0]);
            cp16(smem_u32(&Bs[nb][b_kk1][b_c1]), &Bm[(size_t)(k0 + b_kk1)*ND + bn0 + b_c1]);
            CP_COMMIT();
        }
        float loc[4][8];
        #pragma unroll
        for (int i = 0; i < 4; i++)
            #pragma unroll
            for (int j = 0; j < 8; j++) loc[i][j] = 0.f;
        #pragma unroll
        for (int kk = 0; kk < BK; kk++) {
            float4 aq = *reinterpret_cast<const float4*>(&As[buf][kk][ty*4]);
            float a0 = aq.x, a1 = aq.y, a2 = aq.z, a3 = aq.w;
            float4 q0 = *reinterpret_cast<const float4*>(&Bs[buf][kk][tx*8]);
            float4 q1 = *reinterpret_cast<const float4*>(&Bs[buf][kk][tx*8+4]);
            float bb[8] = {q0.x,q0.y,q0.z,q0.w,q1.x,q1.y,q1.z,q1.w};
            #pragma unroll
            for (int j = 0; j < 8; j++) {
                loc[0][j] = __fmaf_rn(a0, bb[j], loc[0][j]);
                loc[1][j] = __fmaf_rn(a1, bb[j], loc[1][j]);
                loc[2][j] = __fmaf_rn(a2, bb[j], loc[2][j]);
                loc[3][j] = __fmaf_rn(a3, bb[j], loc[3][j]);
            }
        }
        #pragma unroll
        for (int i = 0; i < 4; i++)
            #pragma unroll
            for (int j = 0; j < 8; j++)
                acc[i][j] = __fadd_rn(acc[i][j], loc[i][j]);
        __syncthreads();
    }
    float* P = g_part + (size_t)z * MROWS * ND;
    #pragma unroll
    for (int i = 0; i < 4; i++)
        #pragma unroll
        for (int j = 0; j < 8; j++)
            P[(size_t)(bm0 + ty*4 + i) * ND + bn0 + tx*8 + j] = acc[i][j];
}

// ---------------- reduce split-K partials (fixed 8-way pairwise tree) -------
__global__ __launch_bounds__(256) void reduce_kernel() {
    const size_t S = (size_t)MROWS * ND / 4;   // float4 count
    size_t i = (size_t)blockIdx.x * 256 + threadIdx.x;
    if (i >= S) return;
    const float4* p = reinterpret_cast<const float4*>(g_part) + i;
    float4 v[8];
    #pragma unroll
    for (int z = 0; z < 8; z++) v[z] = p[z * S];
    float4 o;
    #define RED(c) o.c = __fadd_rn( \
        __fadd_rn(__fadd_rn(v[0].c, v[1].c), __fadd_rn(v[2].c, v[3].c)), \
        __fadd_rn(__fadd_rn(v[4].c, v[5].c), __fadd_rn(v[6].c, v[7].c)))
    RED(x); RED(y); RED(z); RED(w);
    #undef RED
    reinterpret_cast<float4*>(g_Tmat)[i] = o;
}

// ---------------- GEMM2 (+fused hist1): single-shot smem, K=64 --------------
__global__ __launch_bounds__(256, 2) void gemm2_kernel(float* __restrict__ outA) {
    extern __shared__ float smem[];
    float* As = smem;                         // [64][128]
    float* Bsm = smem + 64*128;               // [64][128]
    unsigned* sh_hist = (unsigned*)(smem + 2*64*128);  // [4096]
    int b = blockIdx.z;
    const float* AT  = g_XnT + (size_t)b * FF * ND;
    const float* Bmm = g_Tmat + (size_t)b * FF * ND;
    float* C = outA + (size_t)b * NSQ;
    int tid = threadIdx.x;
    int tx = tid & 15, ty = tid >> 4;
    int bm0 = blockIdx.y * 128, bn0 = blockIdx.x * 128;

    #pragma unroll
    for (int r = 0; r < 8; r++) {
        int idx = tid + r*256;                // 0..2047
        int kk = idx >> 5, c4 = (idx & 31) * 4;
        cp16(smem_u32(&As[kk*128 + c4]),  &AT[(size_t)kk*ND + bm0 + c4]);
        cp16(smem_u32(&Bsm[kk*128 + c4]), &Bmm[(size_t)kk*ND + bn0 + c4]);
    }
    CP_COMMIT();
    for (int i = tid; i < 4096; i += 256) sh_hist[i] = 0;

    float acc[8][8];
    #pragma unroll
    for (int i = 0; i < 8; i++)
        #pragma unroll
        for (int j = 0; j < 8; j++) acc[i][j] = 0.f;

    CP_WAIT0();
    __syncthreads();

    #pragma unroll 16
    for (int kk = 0; kk < FF; kk++) {
        float4 a0 = *reinterpret_cast<const float4*>(&As[kk*128 + ty*8]);
        float4 a1 = *reinterpret_cast<const float4*>(&As[kk*128 + ty*8 + 4]);
        float av[8] = {a0.x,a0.y,a0.z,a0.w,a1.x,a1.y,a1.z,a1.w};
        float4 q0 = *reinterpret_cast<const float4*>(&Bsm[kk*128 + tx*8]);
        float4 q1 = *reinterpret_cast<const float4*>(&Bsm[kk*128 + tx*8 + 4]);
        float bb[8] = {q0.x,q0.y,q0.z,q0.w,q1.x,q1.y,q1.z,q1.w};
        #pragma unroll
        for (int i = 0; i < 8; i++)
            #pragma unroll
            for (int j = 0; j < 8; j++)
                acc[i][j] = __fmaf_rn(av[i], bb[j], acc[i][j]);
    }
    int lane = tid & 31;
    #pragma unroll
    for (int i = 0; i < 8; i++) {
        float4 o0 = make_float4(acc[i][0], acc[i][1], acc[i][2], acc[i][3]);
        float4 o1 = make_float4(acc[i][4], acc[i][5], acc[i][6], acc[i][7]);
        size_t rowbase = (size_t)(bm0 + ty*8 + i) * ND + bn0 + tx*8;
        *reinterpret_cast<float4*>(&C[rowbase])     = o0;
        *reinterpret_cast<float4*>(&C[rowbase + 4]) = o1;
        #pragma unroll
        for (int j = 0; j < 8; j++) {
            unsigned bin = f2o(acc[i][j]) >> 20;
            unsigned mm = __match_any_sync(0xffffffffu, bin);
            if (lane == (__ffs(mm) - 1)) atomicAdd(&sh_hist[bin], (unsigned)__popc(mm));
        }
    }
    __syncthreads();
    for (int i = tid; i < 4096; i += 256) {
        unsigned c = sh_hist[i];
        if (c) atomicAdd(&g_hist1[b*4096 + i], c);
    }
}

// ---------------- parallel block select over a histogram --------------------
__device__ __forceinline__ void block_select(const unsigned* __restrict__ h, int NB,
                                             unsigned prev, unsigned k,
                                             unsigned* ps, unsigned* res) {
    int t = threadIdx.x;
    int CH = NB >> 8;
    unsigned csum = 0;
    for (int j = 0; j < CH; j++) csum += h[NB - 1 - (t*CH + j)];
    ps[t] = csum;
    __syncthreads();
    #pragma unroll
    for (int off = 1; off < 256; off <<= 1) {
        unsigned v = (t >= off) ? ps[t - off] : 0u;
        __syncthreads();
        ps[t] += v;
        __syncthreads();
    }
    unsigned excl = ps[t] - csum;
    unsigned cum = prev + excl;
    if (t == 0) { res[0] = 0u; res[1] = prev; }
    __syncthreads();
    if (cum < k && cum + csum >= k) {
        for (int j = 0; j < CH; j++) {
            int bin = NB - 1 - (t*CH + j);
            unsigned c = h[bin];
            if (cum + c >= k) { res[0] = (unsigned)bin; res[1] = cum; break; }
            cum += c;
        }
    }
    __syncthreads();
}

// ---------------- hist2 + candidate compaction (derives bin1 in-block) ------
__global__ __launch_bounds__(256) void hist2_kernel(const float* __restrict__ a) {
    __shared__ unsigned ps[256]; __shared__ unsigned res[2];
    __shared__ unsigned sbin1[BB];
    // every block re-derives bin1 per batch (deterministic, identical result)
    for (int b = 0; b < BB; b++) {
        block_select(g_hist1 + b*4096, 4096, 0u, (unsigned)g_k[b], ps, res);
        if (threadIdx.x == 0) sbin1[b] = res[0];
        __syncthreads();
    }
    const float4* a4 = reinterpret_cast<const float4*>(a);
    size_t tot = (size_t)BB * NSQ / 4;
    int lane = threadIdx.x & 31;
    for (size_t i = (size_t)blockIdx.x*blockDim.x + threadIdx.x; i < tot;
         i += (size_t)gridDim.x * blockDim.x) {
        int b = (int)(i >> 20);
        unsigned bin1 = sbin1[b];
        float4 v = a4[i];
        float vals[4] = {v.x, v.y, v.z, v.w};
        #pragma unroll
        for (int j = 0; j < 4; j++) {
            unsigned o = f2o(vals[j]);
            bool m = (o >> 20) == bin1;
            unsigned bal = __ballot_sync(0xffffffffu, m);
            if (bal) {
                int leader = __ffs(bal) - 1;
                unsigned base = 0;
                if (lane == leader) base = atomicAdd(&g_cand_cnt[b], (unsigned)__popc(bal));
                base = __shfl_sync(0xffffffffu, base, leader);
                if (m) {
                    unsigned pos = base + __popc(bal & ((1u << lane) - 1u));
                    if (pos < CAP) g_cand[b*CAP + pos] = o;
                    atomicAdd(&g_hist2[(b << 12) + ((o >> 8) & 4095)], 1u);
                }
            }
        }
    }
}

// ---------------- select: derive bin1 + scan2 + candidate hist3 + scan3 -----
__global__ __launch_bounds__(256) void select_kernel() {
    __shared__ unsigned ps[256]; __shared__ unsigned res[2];
    __shared__ unsigned h3[256];
    int b = blockIdx.x;
    unsigned k = (unsigned)g_k[b];
    block_select(g_hist1 + b*4096, 4096, 0u, k, ps, res);
    unsigned bin1 = res[0], above1 = res[1];
    block_select(g_hist2 + b*4096, 4096, above1, k, ps, res);
    unsigned bin2 = res[0], above2 = res[1];
    h3[threadIdx.x] = 0;
    __syncthreads();
    unsigned cnt = g_cand_cnt[b];
    if (cnt > CAP) cnt = CAP;
    const unsigned* cl = g_cand + b*CAP;
    for (unsigned i = threadIdx.x; i < cnt; i += 256) {
        unsigned o = cl[i];
        if (((o >> 8) & 4095) == bin2) atomicAdd(&h3[o & 255], 1u);
    }
    __syncthreads();
    block_select(h3, 256, above2, k, ps, res);
    if (threadIdx.x == 0)
        g_thresh[b] = (bin1 << 20) | (bin2 << 8) | res[0];
}

// ---------------- mask = ordered(a) >= T, plus diagonal ----------------
__global__ __launch_bounds__(256) void mask_kernel(const float* __restrict__ a, float* __restrict__ m) {
    const float4* a4 = reinterpret_cast<const float4*>(a);
    float4* m4 = reinterpret_cast<float4*>(m);
    size_t tot = (size_t)BB * NSQ / 4;
    for (size_t i = (size_t)blockIdx.x*blockDim.x + threadIdx.x; i < tot;
         i += (size_t)gridDim.x * blockDim.x) {
        int b = (int)(i >> 20);
        unsigned T = g_thresh[b];
        size_t e = (i & ((1u << 20) - 1)) * 4;
        int row = (int)(e >> 11);
        int col = (int)(e & (ND - 1));
        float4 v = a4[i];
        float4 o;
        o.x = (f2o(v.x) >= T || row == col)     ? 1.0f : 0.0f;
        o.y = (f2o(v.y) >= T || row == col + 1) ? 1.0f : 0.0f;
        o.z = (f2o(v.z) >= T || row == col + 2) ? 1.0f : 0.0f;
        o.w = (f2o(v.w) >= T || row == col + 3) ? 1.0f : 0.0f;
        m4[i] = o;
    }
}

// ---------------- launch ----------------
extern "C" void kernel_launch(void* const* d_in, const int* in_sizes, int n_in,
                              void* d_out, int out_size) {
    const float* x_seq = (const float*)d_in[0];
    const float* prior = (const float*)d_in[1];
    const float* w1 = (const float*)d_in[2];
    const float* b1 = (const float*)d_in[3];
    const float* w2 = (const float*)d_in[4];
    const float* b2 = (const float*)d_in[5];
    const float* w3 = (const float*)d_in[6];
    const float* b3 = (const float*)d_in[7];
    const float* w4 = (const float*)d_in[8];
    const float* b4 = (const float*)d_in[9];
    const float* wout = (const float*)d_in[10];
    const float* bout = (const float*)d_in[11];

    float* out_mask = (float*)d_out;
    float* out_a    = out_mask + (size_t)BB * NSQ;

    static cudaStream_t s_net = nullptr;
    static cudaEvent_t  s_evFork = nullptr, s_evJoin = nullptr;
    if (s_net == nullptr) {
        cudaFuncSetAttribute(gemm2_kernel,
                             cudaFuncAttributeMaxDynamicSharedMemorySize, 81920);
        cudaStreamCreateWithFlags(&s_net, cudaStreamNonBlocking);
        cudaEventCreateWithFlags(&s_evFork, cudaEventDisableTiming);
        cudaEventCreateWithFlags(&s_evJoin, cudaEventDisableTiming);
    }

    // main (capture) stream: stream 0 of this call context
    prep_kernel<<<BB*LL + 256 + 8, 256>>>(x_seq);

    // fork: net runs concurrently with the GEMM chain (it only feeds g_k,
    // first consumed by hist2_kernel)
    cudaEventRecord(s_evFork, 0);
    cudaStreamWaitEvent(s_net, s_evFork, 0);
    net_kernel<<<BB, 256, 0, s_net>>>(w1, b1, w2, b2, w3, b3, w4, b4, wout, bout);
    cudaEventRecord(s_evJoin, s_net);

    gemm1_kernel<<<dim3(ND/128, BB, KSPLIT), 256>>>(prior);
    reduce_kernel<<<(MROWS*ND/4 + 255)/256, 256>>>();
    gemm2_kernel<<<dim3(ND/128, ND/128, BB), 256, 81920>>>(out_a);

    // join net before anything reads g_k
    cudaStreamWaitEvent(0, s_evJoin, 0);

    hist2_kernel<<<8192, 256>>>(out_a);
    select_kernel<<<BB, 256>>>();
    mask_kernel<<<8192, 256>>>(out_a, out_mask);
}

// round 12
// speedup vs baseline: 1.2749x; 1.2749x over previous
#include <cuda_runtime.h>
#include <math.h>

#define BB 8
#define LL 20
#define ND 2048           // N
#define FF 64             // F
#define NSQ (ND*ND)       // 4194304 = 2^22
#define CAP (1<<19)       // candidate capacity per batch
#define KSPLIT 8
#define MROWS (BB*FF)     // 512

// ---------------- scratch (static device, no allocation) ----------------
__device__ double g_m2[BB*LL*FF];
__device__ int    g_k[BB];
__device__ float  g_Xn [BB*ND*FF];        // normalized x_last, [b][n][f]
__device__ float  g_XnT[BB*FF*ND];        // transposed,        [b*64+f][n]
__device__ float  g_Tmat[MROWS*ND];       // t = Xn^T @ prior
__device__ float  g_part[KSPLIT*MROWS*ND];// split-K partials (33.5 MB)
__device__ unsigned g_hist1[BB*4096];
__device__ unsigned long long g_cand[BB*CAP];   // (idx<<20)|low20
__device__ unsigned g_cand_cnt[BB];
__device__ unsigned g_bin1[BB], g_above1[BB];
__device__ unsigned g_tlow[BB];           // low-20 bits of threshold

__device__ __forceinline__ unsigned f2o(float f) {
    unsigned u = __float_as_uint(f);
    return (u & 0x80000000u) ? ~u : (u | 0x80000000u);
}
__device__ __forceinline__ unsigned smem_u32(const void* p) {
    return (unsigned)__cvta_generic_to_shared(p);
}
__device__ __forceinline__ void cp16(unsigned dst, const void* src) {
    asm volatile("cp.async.cg.shared.global [%0], [%1], 16;\n" :: "r"(dst), "l"(src));
}
#define CP_COMMIT() asm volatile("cp.async.commit_group;\n" ::: "memory")
#define CP_WAIT0()  asm volatile("cp.async.wait_group 0;\n" ::: "memory")
#define CP_WAIT1()  asm volatile("cp.async.wait_group 1;\n" ::: "memory")

// ---------------- prep: mean (0..159) + norm (160..415) + zero (416..423) ---
__global__ __launch_bounds__(256) void prep_kernel(const float* __restrict__ x_seq) {
    int tid = threadIdx.x;
    if (blockIdx.x < BB*LL) {
        __shared__ double p[4][64];
        int bl = blockIdx.x;
        int f = tid & 63, j = tid >> 6;
        const float* base = x_seq + (size_t)bl * ND * FF;
        double s = 0.0;
        int n0 = j * 512;
        for (int n = n0; n < n0 + 512; n++) s += (double)base[(size_t)n * FF + f];
        p[j][f] = s;
        __syncthreads();
        if (j == 0) {
            double t = (p[0][f] + p[1][f]) + (p[2][f] + p[3][f]);
            g_m2[bl * FF + f] = t * (1.0 / ND);
        }
    } else if (blockIdx.x < BB*LL + 256) {
        __shared__ float sm[64][65];
        int bid = blockIdx.x - BB*LL;
        int warp = tid >> 5, lane = tid & 31;
        int b = bid >> 5;
        int n0 = (bid & 31) * 64;
        const float* xb = x_seq + ((size_t)(b*LL + (LL-1)) * ND + n0) * FF;
        for (int r = warp; r < 64; r += 8) {
            const float* row = xb + (size_t)r * FF;
            float v0 = row[lane], v1 = row[lane + 32];
            double ss = (double)v0*(double)v0 + (double)v1*(double)v1;
            #pragma unroll
            for (int o = 16; o; o >>= 1) ss += __shfl_xor_sync(0xffffffffu, ss, o);
            double d = sqrt(ss);
            if (d < 1e-12) d = 1e-12;
            float y0 = (float)((double)v0 / d), y1 = (float)((double)v1 / d);
            sm[r][lane] = y0; sm[r][lane + 32] = y1;
            size_t rb = (size_t)(b*ND + n0 + r) * FF;
            g_Xn[rb + lane]      = y0;
            g_Xn[rb + lane + 32] = y1;
        }
        __syncthreads();
        int f = tid >> 2, q = (tid & 3) * 16;
        float4* dst = reinterpret_cast<float4*>(&g_XnT[(size_t)(b*FF + f) * ND + n0 + q]);
        #pragma unroll
        for (int c = 0; c < 4; c++) {
            float4 v;
            v.x = sm[q + c*4 + 0][f];
            v.y = sm[q + c*4 + 1][f];
            v.z = sm[q + c*4 + 2][f];
            v.w = sm[q + c*4 + 3][f];
            dst[c] = v;
        }
    } else {
        int z = blockIdx.x - (BB*LL + 256);
        for (int i = z*256 + tid; i < BB*4096; i += 2048) g_hist1[i] = 0;
        if (z == 0 && tid < BB) g_cand_cnt[tid] = 0;
    }
}

// ---------------- tiny conv net -> k[b] (bit-exact, frozen) -----------------
__global__ __launch_bounds__(256) void net_kernel(
    const float* __restrict__ w1, const float* __restrict__ b1,
    const float* __restrict__ w2, const float* __restrict__ b2,
    const float* __restrict__ w3, const float* __restrict__ b3,
    const float* __restrict__ w4, const float* __restrict__ b4,
    const float* __restrict__ wout, const float* __restrict__ bout)
{
    __shared__ double sm[22][66];
    __shared__ double wsum[32][8];
    int tid = threadIdx.x;
    int lane = tid & 31, warp = tid >> 5;
    int b = blockIdx.x;

    for (int i = tid; i < 22*66; i += 256) ((double*)sm)[i] = 0.0;
    __syncthreads();
    for (int i = tid; i < LL*FF; i += 256) {
        int h = i / FF, w = i % FF;
        sm[h+1][w+1] = g_m2[(b*LL + h)*FF + w];
    }
    __syncthreads();

    double s[32];
    #pragma unroll
    for (int q = 0; q < 32; q++) s[q] = 0.0;

    for (int i = tid; i < LL*FF; i += 256) {
        int h = i / FF + 1, w = i % FF + 1;
        double c   = sm[h][w];
        double lft = sm[h][w-1], rgt = sm[h][w+1];
        double up  = sm[h-1][w], dn  = sm[h+1][w];
        double ul  = sm[h-1][w-1], ur = sm[h-1][w+1];
        double dl  = sm[h+1][w-1], dr = sm[h+1][w+1];
        #pragma unroll
        for (int ch = 0; ch < 8; ch++) {
            double v1 = (double)w1[ch]*c + (double)b1[ch];
            double v2 = (double)w2[ch*3+0]*lft + (double)w2[ch*3+1]*c + (double)w2[ch*3+2]*rgt + (double)b2[ch];
            double v3 = (double)w3[ch*3+0]*up  + (double)w3[ch*3+1]*c + (double)w3[ch*3+2]*dn  + (double)b3[ch];
            double v4 = (double)w4[ch*9+0]*ul + (double)w4[ch*9+1]*up + (double)w4[ch*9+2]*ur
                      + (double)w4[ch*9+3]*lft+ (double)w4[ch*9+4]*c  + (double)w4[ch*9+5]*rgt
                      + (double)w4[ch*9+6]*dl + (double)w4[ch*9+7]*dn + (double)w4[ch*9+8]*dr + (double)b4[ch];
            float f1 = (float)v1, f2 = (float)v2, f3 = (float)v3, f4 = (float)v4;
            s[ch]      += (double)(0.5f*f1*(1.0f + erff(f1*0.70710678f)));
            s[8  + ch] += (double)(0.5f*f2*(1.0f + erff(f2*0.70710678f)));
            s[16 + ch] += (double)(0.5f*f3*(1.0f + erff(f3*0.70710678f)));
            s[24 + ch] += (double)(0.5f*f4*(1.0f + erff(f4*0.70710678f)));
        }
    }
    #pragma unroll
    for (int q = 0; q < 32; q++) {
        double v = s[q];
        #pragma unroll
        for (int o = 16; o; o >>= 1) v += __shfl_down_sync(0xffffffffu, v, o);
        if (lane == 0) wsum[q][warp] = v;
    }
    __syncthreads();
    if (tid == 0) {
        double logit = (double)bout[0];
        for (int q = 0; q < 32; q++) {
            double t = 0.0;
            for (int w = 0; w < 8; w++) t += wsum[q][w];
            logit += (t * (1.0/(LL*FF))) * (double)wout[q];
        }
        double sig  = 1.0 / (1.0 + exp(-logit));
        double keep = 0.2 * sig;
        if (keep < 0.02) keep = 0.02;
        if (keep > 1.0)  keep = 1.0;
        float kf = __fmul_rn((float)keep, 4194304.0f);
        int k = (int)ceilf(kf);
        if (k < 1) k = 1;
        if (k > NSQ) k = NSQ;
        g_k[b] = k;
    }
}

// ---------------- GEMM1 split-K(8): part[z] = XnT @ prior, 3-stage pipeline -
__global__ __launch_bounds__(256, 2) void gemm1_kernel(const float* __restrict__ Bm) {
    const int BK = 16;
    __shared__ float As[3][BK][72];
    __shared__ __align__(16) float Bs[3][BK][128];
    int tid = threadIdx.x;
    int tx = tid & 15, ty = tid >> 4;
    int b = blockIdx.y, z = blockIdx.z;
    int bm0 = b * 64, bn0 = blockIdx.x * 128;
    int kbase = z * (ND / KSPLIT);

    float acc[4][8];
    #pragma unroll
    for (int i = 0; i < 4; i++)
        #pragma unroll
        for (int j = 0; j < 8; j++) acc[i][j] = 0.f;

    int a_kk = tid >> 4, a_f4 = (tid & 15) * 4;
    int b_kk0 = tid >> 5,         b_c0 = (tid & 31) * 4;
    int b_kk1 = 8 + (tid >> 5),   b_c1 = b_c0;

    const int T = (ND / KSPLIT) / BK;       // 16 tiles
    #pragma unroll
    for (int pt = 0; pt < 2; pt++) {
        int k0 = kbase + pt * BK;
        cp16(smem_u32(&As[pt][a_kk][a_f4]),  &g_Xn[((size_t)b*ND + k0 + a_kk)*FF + a_f4]);
        cp16(smem_u32(&Bs[pt][b_kk0][b_c0]), &Bm[(size_t)(k0 + b_kk0)*ND + bn0 + b_c0]);
        cp16(smem_u32(&Bs[pt][b_kk1][b_c1]), &Bm[(size_t)(k0 + b_kk1)*ND + bn0 + b_c1]);
        CP_COMMIT();
    }

    for (int t = 0; t < T; t++) {
        if (t == T - 1) { CP_WAIT0(); } else { CP_WAIT1(); }
        __syncthreads();
        int buf = t % 3;
        if (t + 2 < T) {
            int k0 = kbase + (t + 2) * BK, nb = (t + 2) % 3;
            cp16(smem_u32(&As[nb][a_kk][a_f4]),  &g_Xn[((size_t)b*ND + k0 + a_kk)*FF + a_f4]);
            cp16(smem_u32(&Bs[nb][b_kk0][b_c0]), &Bm[(size_t)(k0 + b_kk0)*ND + bn0 + b_c0]);
            cp16(smem_u32(&Bs[nb][b_kk1][b_c1]), &Bm[(size_t)(k0 + b_kk1)*ND + bn0 + b_c1]);
            CP_COMMIT();
        }
        float loc[4][8];
        #pragma unroll
        for (int i = 0; i < 4; i++)
            #pragma unroll
            for (int j = 0; j < 8; j++) loc[i][j] = 0.f;
        #pragma unroll
        for (int kk = 0; kk < BK; kk++) {
            float4 aq = *reinterpret_cast<const float4*>(&As[buf][kk][ty*4]);
            float a0 = aq.x, a1 = aq.y, a2 = aq.z, a3 = aq.w;
            float4 q0 = *reinterpret_cast<const float4*>(&Bs[buf][kk][tx*8]);
            float4 q1 = *reinterpret_cast<const float4*>(&Bs[buf][kk][tx*8+4]);
            float bb[8] = {q0.x,q0.y,q0.z,q0.w,q1.x,q1.y,q1.z,q1.w};
            #pragma unroll
            for (int j = 0; j < 8; j++) {
                loc[0][j] = __fmaf_rn(a0, bb[j], loc[0][j]);
                loc[1][j] = __fmaf_rn(a1, bb[j], loc[1][j]);
                loc[2][j] = __fmaf_rn(a2, bb[j], loc[2][j]);
                loc[3][j] = __fmaf_rn(a3, bb[j], loc[3][j]);
            }
        }
        #pragma unroll
        for (int i = 0; i < 4; i++)
            #pragma unroll
            for (int j = 0; j < 8; j++)
                acc[i][j] = __fadd_rn(acc[i][j], loc[i][j]);
        __syncthreads();
    }
    float* P = g_part + (size_t)z * MROWS * ND;
    #pragma unroll
    for (int i = 0; i < 4; i++)
        #pragma unroll
        for (int j = 0; j < 8; j++)
            P[(size_t)(bm0 + ty*4 + i) * ND + bn0 + tx*8 + j] = acc[i][j];
}

// ---------------- reduce split-K partials (fixed 8-way pairwise tree) -------
__global__ __launch_bounds__(256) void reduce_kernel() {
    const size_t S = (size_t)MROWS * ND / 4;
    size_t i = (size_t)blockIdx.x * 256 + threadIdx.x;
    if (i >= S) return;
    const float4* p = reinterpret_cast<const float4*>(g_part) + i;
    float4 v[8];
    #pragma unroll
    for (int z = 0; z < 8; z++) v[z] = p[z * S];
    float4 o;
    #define RED(c) o.c = __fadd_rn( \
        __fadd_rn(__fadd_rn(v[0].c, v[1].c), __fadd_rn(v[2].c, v[3].c)), \
        __fadd_rn(__fadd_rn(v[4].c, v[5].c), __fadd_rn(v[6].c, v[7].c)))
    RED(x); RED(y); RED(z); RED(w);
    #undef RED
    reinterpret_cast<float4*>(g_Tmat)[i] = o;
}

// ---------------- GEMM2 (+fused hist1): single-shot smem, K=64 --------------
__global__ __launch_bounds__(256, 2) void gemm2_kernel(float* __restrict__ outA) {
    extern __shared__ float smem[];
    float* As = smem;                         // [64][128]
    float* Bsm = smem + 64*128;               // [64][128]
    unsigned* sh_hist = (unsigned*)(smem + 2*64*128);  // [4096]
    int b = blockIdx.z;
    const float* AT  = g_XnT + (size_t)b * FF * ND;
    const float* Bmm = g_Tmat + (size_t)b * FF * ND;
    float* C = outA + (size_t)b * NSQ;
    int tid = threadIdx.x;
    int tx = tid & 15, ty = tid >> 4;
    int bm0 = blockIdx.y * 128, bn0 = blockIdx.x * 128;

    #pragma unroll
    for (int r = 0; r < 8; r++) {
        int idx = tid + r*256;
        int kk = idx >> 5, c4 = (idx & 31) * 4;
        cp16(smem_u32(&As[kk*128 + c4]),  &AT[(size_t)kk*ND + bm0 + c4]);
        cp16(smem_u32(&Bsm[kk*128 + c4]), &Bmm[(size_t)kk*ND + bn0 + c4]);
    }
    CP_COMMIT();
    for (int i = tid; i < 4096; i += 256) sh_hist[i] = 0;

    float acc[8][8];
    #pragma unroll
    for (int i = 0; i < 8; i++)
        #pragma unroll
        for (int j = 0; j < 8; j++) acc[i][j] = 0.f;

    CP_WAIT0();
    __syncthreads();

    #pragma unroll 16
    for (int kk = 0; kk < FF; kk++) {
        float4 a0 = *reinterpret_cast<const float4*>(&As[kk*128 + ty*8]);
        float4 a1 = *reinterpret_cast<const float4*>(&As[kk*128 + ty*8 + 4]);
        float av[8] = {a0.x,a0.y,a0.z,a0.w,a1.x,a1.y,a1.z,a1.w};
        float4 q0 = *reinterpret_cast<const float4*>(&Bsm[kk*128 + tx*8]);
        float4 q1 = *reinterpret_cast<const float4*>(&Bsm[kk*128 + tx*8 + 4]);
        float bb[8] = {q0.x,q0.y,q0.z,q0.w,q1.x,q1.y,q1.z,q1.w};
        #pragma unroll
        for (int i = 0; i < 8; i++)
            #pragma unroll
            for (int j = 0; j < 8; j++)
                acc[i][j] = __fmaf_rn(av[i], bb[j], acc[i][j]);
    }
    int lane = tid & 31;
    #pragma unroll
    for (int i = 0; i < 8; i++) {
        float4 o0 = make_float4(acc[i][0], acc[i][1], acc[i][2], acc[i][3]);
        float4 o1 = make_float4(acc[i][4], acc[i][5], acc[i][6], acc[i][7]);
        size_t rowbase = (size_t)(bm0 + ty*8 + i) * ND + bn0 + tx*8;
        *reinterpret_cast<float4*>(&C[rowbase])     = o0;
        *reinterpret_cast<float4*>(&C[rowbase + 4]) = o1;
        #pragma unroll
        for (int j = 0; j < 8; j++) {
            unsigned bin = f2o(acc[i][j]) >> 20;
            unsigned mm = __match_any_sync(0xffffffffu, bin);
            if (lane == (__ffs(mm) - 1)) atomicAdd(&sh_hist[bin], (unsigned)__popc(mm));
        }
    }
    __syncthreads();
    for (int i = tid; i < 4096; i += 256) {
        unsigned c = sh_hist[i];
        if (c) atomicAdd(&g_hist1[b*4096 + i], c);
    }
}

// ---------------- parallel block select over a histogram --------------------
__device__ __forceinline__ void block_select(const unsigned* __restrict__ h, int NB,
                                             unsigned prev, unsigned k,
                                             unsigned* ps, unsigned* res) {
    int t = threadIdx.x;
    int CH = NB >> 8;
    unsigned csum = 0;
    for (int j = 0; j < CH; j++) csum += h[NB - 1 - (t*CH + j)];
    ps[t] = csum;
    __syncthreads();
    #pragma unroll
    for (int off = 1; off < 256; off <<= 1) {
        unsigned v = (t >= off) ? ps[t - off] : 0u;
        __syncthreads();
        ps[t] += v;
        __syncthreads();
    }
    unsigned excl = ps[t] - csum;
    unsigned cum = prev + excl;
    if (t == 0) { res[0] = 0u; res[1] = prev; }
    __syncthreads();
    if (cum < k && cum + csum >= k) {
        for (int j = 0; j < CH; j++) {
            int bin = NB - 1 - (t*CH + j);
            unsigned c = h[bin];
            if (cum + c >= k) { res[0] = (unsigned)bin; res[1] = cum; break; }
            cum += c;
        }
    }
    __syncthreads();
}

__global__ __launch_bounds__(256) void scan1_kernel() {
    __shared__ unsigned ps[256]; __shared__ unsigned res[2];
    int b = blockIdx.x;
    block_select(g_hist1 + b*4096, 4096, 0u, (unsigned)g_k[b], ps, res);
    if (threadIdx.x == 0) { g_bin1[b] = res[0]; g_above1[b] = res[1]; }
}

// ---------------- classify: write decided mask bits + compact boundary ------
// One full read of a, one full write of mask. Deferred elements (top12==bin1)
// get a placeholder (diag-aware 0) and are appended as (idx<<20)|low20.
__global__ __launch_bounds__(256) void classify_kernel(const float* __restrict__ a,
                                                       float* __restrict__ m) {
    const float4* a4 = reinterpret_cast<const float4*>(a);
    float4* m4 = reinterpret_cast<float4*>(m);
    size_t tot = (size_t)BB * NSQ / 4;
    int lane = threadIdx.x & 31;
    for (size_t i = (size_t)blockIdx.x*blockDim.x + threadIdx.x; i < tot;
         i += (size_t)gridDim.x * blockDim.x) {
        int b = (int)(i >> 20);
        unsigned bin1 = g_bin1[b];
        size_t e = (i & ((1u << 20) - 1)) * 4;
        int row = (int)(e >> 11);
        int col = (int)(e & (ND - 1));
        float4 v = a4[i];
        float vals[4] = {v.x, v.y, v.z, v.w};
        float ovals[4];
        unsigned defer_mask = 0;
        unsigned lo20[4];
        #pragma unroll
        for (int j = 0; j < 4; j++) {
            unsigned o = f2o(vals[j]);
            unsigned top = o >> 20;
            bool diag = (row == col + j);
            ovals[j] = (top > bin1 || diag) ? 1.0f : 0.0f;
            if (top == bin1) { defer_mask |= (1u << j); lo20[j] = o & 0xFFFFFu; }
        }
        float4 ov = make_float4(ovals[0], ovals[1], ovals[2], ovals[3]);
        m4[i] = ov;
        // warp-aggregated append of deferred elements
        #pragma unroll
        for (int j = 0; j < 4; j++) {
            bool mm = (defer_mask >> j) & 1u;
            unsigned bal = __ballot_sync(0xffffffffu, mm);
            if (bal) {
                int leader = __ffs(bal) - 1;
                unsigned base = 0;
                if (lane == leader) base = atomicAdd(&g_cand_cnt[b], (unsigned)__popc(bal));
                base = __shfl_sync(0xffffffffu, base, leader);
                if (mm) {
                    unsigned pos = base + __popc(bal & ((1u << lane) - 1u));
                    if (pos < CAP)
                        g_cand[b*CAP + pos] =
                            ((unsigned long long)(e + j) << 20) | lo20[j];
                }
            }
        }
    }
}

// ---------------- select: build level-2 hist from candidates + level-3 ------
__global__ __launch_bounds__(256) void select_kernel() {
    __shared__ unsigned ps[256]; __shared__ unsigned res[2];
    __shared__ unsigned h2[4096];
    __shared__ unsigned h3[256];
    int b = blockIdx.x;
    unsigned k = (unsigned)g_k[b];
    unsigned above1 = g_above1[b];
    for (int i = threadIdx.x; i < 4096; i += 256) h2[i] = 0;
    h3[threadIdx.x] = 0;
    __syncthreads();
    unsigned cnt = g_cand_cnt[b];
    if (cnt > CAP) cnt = CAP;
    const unsigned long long* cl = g_cand + b*CAP;
    for (unsigned i = threadIdx.x; i < cnt; i += 256) {
        unsigned lo = (unsigned)(cl[i] & 0xFFFFFu);
        atomicAdd(&h2[lo >> 8], 1u);
    }
    __syncthreads();
    block_select(h2, 4096, above1, k, ps, res);
    unsigned bin2 = res[0], above2 = res[1];
    for (unsigned i = threadIdx.x; i < cnt; i += 256) {
        unsigned lo = (unsigned)(cl[i] & 0xFFFFFu);
        if ((lo >> 8) == bin2) atomicAdd(&h3[lo & 255], 1u);
    }
    __syncthreads();
    block_select(h3, 256, above2, k, ps, res);
    if (threadIdx.x == 0)
        g_tlow[b] = (bin2 << 8) | res[0];
}

// ---------------- fixup: final mask bits for deferred elements --------------
__global__ __launch_bounds__(256) void fixup_kernel(float* __restrict__ m) {
    int b = blockIdx.y;
    unsigned tlow = g_tlow[b];
    unsigned cnt = g_cand_cnt[b];
    if (cnt > CAP) cnt = CAP;
    const unsigned long long* cl = g_cand + b*CAP;
    float* mb = m + (size_t)b * NSQ;
    for (unsigned i = blockIdx.x*256 + threadIdx.x; i < cnt; i += gridDim.x*256) {
        unsigned long long rec = cl[i];
        unsigned lo = (unsigned)(rec & 0xFFFFFu);
        unsigned idx = (unsigned)(rec >> 20);
        int row = idx >> 11, col = idx & (ND - 1);
        mb[idx] = (lo >= tlow || row == col) ? 1.0f : 0.0f;
    }
}

// ---------------- launch ----------------
extern "C" void kernel_launch(void* const* d_in, const int* in_sizes, int n_in,
                              void* d_out, int out_size) {
    const float* x_seq = (const float*)d_in[0];
    const float* prior = (const float*)d_in[1];
    const float* w1 = (const float*)d_in[2];
    const float* b1 = (const float*)d_in[3];
    const float* w2 = (const float*)d_in[4];
    const float* b2 = (const float*)d_in[5];
    const float* w3 = (const float*)d_in[6];
    const float* b3 = (const float*)d_in[7];
    const float* w4 = (const float*)d_in[8];
    const float* b4 = (const float*)d_in[9];
    const float* wout = (const float*)d_in[10];
    const float* bout = (const float*)d_in[11];

    float* out_mask = (float*)d_out;
    float* out_a    = out_mask + (size_t)BB * NSQ;

    static cudaStream_t s_net = nullptr;
    static cudaEvent_t  s_evFork = nullptr, s_evJoin = nullptr;
    if (s_net == nullptr) {
        cudaFuncSetAttribute(gemm2_kernel,
                             cudaFuncAttributeMaxDynamicSharedMemorySize, 81920);
        cudaStreamCreateWithFlags(&s_net, cudaStreamNonBlocking);
        cudaEventCreateWithFlags(&s_evFork, cudaEventDisableTiming);
        cudaEventCreateWithFlags(&s_evJoin, cudaEventDisableTiming);
    }

    prep_kernel<<<BB*LL + 256 + 8, 256>>>(x_seq);

    // fork: net (feeds only g_k) overlaps the GEMM chain
    cudaEventRecord(s_evFork, 0);
    cudaStreamWaitEvent(s_net, s_evFork, 0);
    net_kernel<<<BB, 256, 0, s_net>>>(w1, b1, w2, b2, w3, b3, w4, b4, wout, bout);
    cudaEventRecord(s_evJoin, s_net);

    gemm1_kernel<<<dim3(ND/128, BB, KSPLIT), 256>>>(prior);
    reduce_kernel<<<(MROWS*ND/4 + 255)/256, 256>>>();
    gemm2_kernel<<<dim3(ND/128, ND/128, BB), 256, 81920>>>(out_a);

    cudaStreamWaitEvent(0, s_evJoin, 0);   // join before g_k is read

    scan1_kernel<<<BB, 256>>>();
    classify_kernel<<<8192, 256>>>(out_a, out_mask);
    select_kernel<<<BB, 256>>>();
    fixup_kernel<<<dim3(64, BB), 256>>>(out_mask);
}